// round 1
// baseline (speedup 1.0000x reference)
#include <cuda_runtime.h>
#include <cstddef>

// Problem constants
#define BB 16384
#define DD 256
#define LL 255
#define HH 8

// Tiling
#define TB 64      // batch rows per CTA
#define TL 16      // layers per chunk (== layer lanes)
#define KD 64      // d sub-chunk
#define NT 256     // threads per CTA

// Padded smem strides (floats) for bank-conflict avoidance
#define XS_STR 260   // x tile row stride (row diff 4*260 % 32 = 16 -> spread banks)
#define W1_STR 132   // W1 chunk dd stride (dd*132 % 32 = 4*dd -> 2-way worst on store)
#define W2_STR 68
#define W3_STR 18

#define SMEM_FLOATS (TB*XS_STR + KD*W1_STR + TL*W2_STR + TL*W3_STR + TL*8 + TL*8 + TL*2)
#define SMEM_BYTES  (SMEM_FLOATS * 4)

__device__ __forceinline__ unsigned long long pk2(float a, float b) {
    unsigned long long r;
    asm("mov.b64 %0, {%1, %2};" : "=l"(r) : "f"(a), "f"(b));
    return r;
}
__device__ __forceinline__ void fma2(unsigned long long& d, unsigned long long a, unsigned long long b) {
    asm("fma.rn.f32x2 %0, %1, %2, %0;" : "+l"(d) : "l"(a), "l"(b));
}
__device__ __forceinline__ float2 up2(unsigned long long v) {
    float2 r;
    asm("mov.b64 {%0, %1}, %2;" : "=f"(r.x), "=f"(r.y) : "l"(v));
    return r;
}
// tanh(v) = 1 - 2/(exp(2v)+1). Saturates correctly for |v| large (exp->inf or 0).
// ex2.approx + rcp.approx: ~1e-6 abs error, fine vs 1e-3 threshold.
__device__ __forceinline__ float ftanh(float v) {
    float e = __expf(2.0f * v);
    return 1.0f - __fdividef(2.0f, e + 1.0f);
}

extern __shared__ float smem[];

__global__ void __launch_bounds__(NT, 2) maf_kernel(
    const float* __restrict__ x,   const float* __restrict__ ipar,
    const float* __restrict__ W1,  const float* __restrict__ b1,
    const float* __restrict__ W2,  const float* __restrict__ b2,
    const float* __restrict__ W3,  const float* __restrict__ b3,
    float* __restrict__ out, int out_size)
{
    float* xs  = smem;                     // [TB][XS_STR]
    float* w1s = xs  + TB * XS_STR;        // [KD][W1_STR] : dd*W1_STR + j*8 + h
    float* w2s = w1s + KD * W1_STR;        // [TL][W2_STR] : j*68 + h*8 + k
    float* w3s = w2s + TL * W2_STR;        // [TL][W3_STR] : j*18 + h*2 + k
    float* b1s = w3s + TL * W3_STR;        // [TL][8]
    float* b2s = b1s + TL * 8;             // [TL][8]
    float* b3s = b2s + TL * 8;             // [TL][2]

    const int tid  = threadIdx.x;
    const int j    = tid & 15;             // layer lane within chunk
    const int rg   = tid >> 4;             // row group (4 rows each)
    const int row0 = blockIdx.x * TB;

    // ---- load x tile (coalesced float4) ----
    {
        const float4* xg = (const float4*)(x + (size_t)row0 * DD);
        #pragma unroll
        for (int i = 0; i < (TB * DD / 4) / NT; ++i) {   // 16 iters
            int v  = tid + i * NT;
            int r  = v >> 6;
            int dv = v & 63;
            float4 val = xg[r * (DD / 4) + dv];
            *(float4*)(xs + r * XS_STR + dv * 4) = val;
        }
    }

    unsigned long long acc[4][4];          // 4 rows x 8 h (packed pairs)
    float asum[4] = {0.f, 0.f, 0.f, 0.f};  // per-row alpha partial (this layer lane)

    for (int c = 0; c < 16; ++c) {
        const int l0 = c * TL;
        const int l  = l0 + j;             // this thread's layer (may be LL -> skip)
        __syncthreads();                   // previous chunk's consumers done

        // ---- per-layer small weights for this chunk ----
        for (int v = tid; v < TL * 64; v += NT) {
            int jj = v >> 6, hk = v & 63;
            w2s[jj * W2_STR + hk] = (l0 + jj < LL) ? W2[(l0 + jj) * 64 + hk] : 0.f;
        }
        for (int v = tid; v < TL * 16; v += NT) {
            int jj = v >> 4, hk = v & 15;
            w3s[jj * W3_STR + hk] = (l0 + jj < LL) ? W3[(l0 + jj) * 16 + hk] : 0.f;
        }
        if (tid < TL * 8) {
            int jj = tid >> 3, h = tid & 7;
            b1s[tid] = (l0 + jj < LL) ? b1[(l0 + jj) * 8 + h] : 0.f;
            b2s[tid] = (l0 + jj < LL) ? b2[(l0 + jj) * 8 + h] : 0.f;
        }
        if (tid < TL * 2) {
            int jj = tid >> 1, k = tid & 1;
            b3s[tid] = (l0 + jj < LL) ? b3[(l0 + jj) * 2 + k] : 0.f;
        }

        #pragma unroll
        for (int i = 0; i < 4; ++i) {
            acc[i][0] = 0ull; acc[i][1] = 0ull; acc[i][2] = 0ull; acc[i][3] = 0ull;
        }

        // causal mask: layer l only needs d <= l, so chunk needs d < l0+TL
        const int nsub = (l0 + TL + KD - 1) >> 6;
        for (int s = 0; s < nsub; ++s) {
            const int d0 = s << 6;
            __syncthreads();
            // ---- stream W1 chunk into smem, masked (d > l -> 0) ----
            #pragma unroll
            for (int i = 0; i < 8; ++i) {
                int v   = tid + i * NT;        // float4 index 0..2047
                int jj  = v >> 7;
                int rem = v & 127;
                int dd  = rem >> 1;
                int h4  = (rem & 1) << 2;
                int lL  = l0 + jj;
                int gd  = d0 + dd;
                float4 val = make_float4(0.f, 0.f, 0.f, 0.f);
                if (lL < LL && gd <= lL)
                    val = *(const float4*)(W1 + ((size_t)lL * DD + gd) * HH + h4);
                *(float4*)(w1s + dd * W1_STR + jj * 8 + h4) = val;
            }
            __syncthreads();

            const float* xr0 = xs + (rg * 4 + 0) * XS_STR + d0;
            const float* xr1 = xr0 + XS_STR;
            const float* xr2 = xr1 + XS_STR;
            const float* xr3 = xr2 + XS_STR;
            const float* wp  = w1s + j * 8;
            #pragma unroll 4
            for (int dd = 0; dd < KD; ++dd) {
                ulonglong2 wA = *(const ulonglong2*)(wp + dd * W1_STR);
                ulonglong2 wB = *(const ulonglong2*)(wp + dd * W1_STR + 4);
                float x0 = xr0[dd], x1 = xr1[dd], x2 = xr2[dd], x3 = xr3[dd];
                unsigned long long p0 = pk2(x0, x0), p1 = pk2(x1, x1);
                unsigned long long p2 = pk2(x2, x2), p3 = pk2(x3, x3);
                fma2(acc[0][0], p0, wA.x); fma2(acc[0][1], p0, wA.y);
                fma2(acc[0][2], p0, wB.x); fma2(acc[0][3], p0, wB.y);
                fma2(acc[1][0], p1, wA.x); fma2(acc[1][1], p1, wA.y);
                fma2(acc[1][2], p1, wB.x); fma2(acc[1][3], p1, wB.y);
                fma2(acc[2][0], p2, wA.x); fma2(acc[2][1], p2, wA.y);
                fma2(acc[2][2], p2, wB.x); fma2(acc[2][3], p2, wB.y);
                fma2(acc[3][0], p3, wA.x); fma2(acc[3][1], p3, wA.y);
                fma2(acc[3][2], p3, wB.x); fma2(acc[3][3], p3, wB.y);
            }
        }

        // ---- epilogue: tiny MLP + z write for layer l, rows rg*4..rg*4+3 ----
        if (l < LL) {
            #pragma unroll
            for (int i = 0; i < 4; ++i) {
                float h1v[8];
                #pragma unroll
                for (int hp = 0; hp < 4; ++hp) {
                    float2 a = up2(acc[i][hp]);
                    h1v[2 * hp]     = ftanh(a.x + b1s[j * 8 + 2 * hp]);
                    h1v[2 * hp + 1] = ftanh(a.y + b1s[j * 8 + 2 * hp + 1]);
                }
                unsigned long long a2[4];
                a2[0] = pk2(b2s[j * 8 + 0], b2s[j * 8 + 1]);
                a2[1] = pk2(b2s[j * 8 + 2], b2s[j * 8 + 3]);
                a2[2] = pk2(b2s[j * 8 + 4], b2s[j * 8 + 5]);
                a2[3] = pk2(b2s[j * 8 + 6], b2s[j * 8 + 7]);
                #pragma unroll
                for (int h = 0; h < 8; ++h) {
                    ulonglong2 rA = *(const ulonglong2*)(w2s + j * W2_STR + h * 8);
                    ulonglong2 rB = *(const ulonglong2*)(w2s + j * W2_STR + h * 8 + 4);
                    unsigned long long hp = pk2(h1v[h], h1v[h]);
                    fma2(a2[0], hp, rA.x); fma2(a2[1], hp, rA.y);
                    fma2(a2[2], hp, rB.x); fma2(a2[3], hp, rB.y);
                }
                float mu = b3s[j * 2 + 0], al = b3s[j * 2 + 1];
                #pragma unroll
                for (int hp = 0; hp < 4; ++hp) {
                    float2 p = up2(a2[hp]);
                    float h2a = ftanh(p.x), h2b = ftanh(p.y);
                    mu += h2a * w3s[j * W3_STR + (2 * hp) * 2]
                        + h2b * w3s[j * W3_STR + (2 * hp + 1) * 2];
                    al += h2a * w3s[j * W3_STR + (2 * hp) * 2 + 1]
                        + h2b * w3s[j * W3_STR + (2 * hp + 1) * 2 + 1];
                }
                int row = rg * 4 + i;
                float xn = xs[row * XS_STR + (l + 1)];
                float zv = (xn - mu) * __expf(-al);
                // z column l+1, reversed output -> column 254 - l
                out[(size_t)(row0 + row) * DD + (254 - l)] = zv;
                asum[i] += al;
            }
        }
    }

    // ---- reduce alpha partials across the 16 layer lanes; finalize ----
    __syncthreads();
    #pragma unroll
    for (int i = 0; i < 4; ++i)
        w1s[(rg * 4 + i) * 17 + j] = asum[i];   // reuse w1s as [64][17] scratch
    __syncthreads();
    if (tid < TB) {
        int row = tid;
        float ssum = 0.f;
        #pragma unroll
        for (int jj = 0; jj < 16; ++jj) ssum += w1s[row * 17 + jj];
        float ip0 = ipar[0], ip1 = ipar[1];
        // z column 0 (initial param), reversed -> output column 255
        out[(size_t)(row0 + row) * DD + 255] = (xs[row * XS_STR] - ip0) * __expf(-ip1);
        if (out_size > BB * DD)
            out[(size_t)BB * DD + row0 + row] = -(ip1 + ssum);
    }
}

extern "C" void kernel_launch(void* const* d_in, const int* in_sizes, int n_in,
                              void* d_out, int out_size)
{
    const float* x    = (const float*)d_in[0];
    const float* ipar = (const float*)d_in[1];
    const float* W1   = (const float*)d_in[2];
    const float* b1   = (const float*)d_in[3];
    const float* W2   = (const float*)d_in[4];
    const float* b2   = (const float*)d_in[5];
    const float* W3   = (const float*)d_in[6];
    const float* b3   = (const float*)d_in[7];
    float* out = (float*)d_out;

    cudaFuncSetAttribute(maf_kernel, cudaFuncAttributeMaxDynamicSharedMemorySize, SMEM_BYTES);
    maf_kernel<<<BB / TB, NT, SMEM_BYTES>>>(x, ipar, W1, b1, W2, b2, W3, b3, out, out_size);
}

// round 2
// speedup vs baseline: 1.4983x; 1.4983x over previous
#include <cuda_runtime.h>
#include <cstddef>

// Problem constants
#define BB 16384
#define DD 256
#define LL 255
#define HH 8

// Tiling
#define TB 128     // batch rows per CTA
#define TL 16      // layers per chunk
#define KD 32      // d sub-chunk granularity
#define NT 256     // threads per CTA

// Padded smem strides (floats)
#define XS_STR 260   // rows: bank = 4*rg -> conflict-free for 8 consecutive rg
#define W1_STR 132   // dd stride; loads are j-indexed (32B apart) -> 1 phase
#define W2_STR 68
#define W3_STR 18

#define SMEM_FLOATS (TB*XS_STR + KD*W1_STR + TL*W2_STR + TL*W3_STR + TL*8 + TL*8 + TL*2)
#define SMEM_BYTES  (SMEM_FLOATS * 4)

__device__ __forceinline__ unsigned long long pk2(float a, float b) {
    unsigned long long r;
    asm("mov.b64 %0, {%1, %2};" : "=l"(r) : "f"(a), "f"(b));
    return r;
}
__device__ __forceinline__ void fma2(unsigned long long& d, unsigned long long a, unsigned long long b) {
    asm("fma.rn.f32x2 %0, %1, %2, %0;" : "+l"(d) : "l"(a), "l"(b));
}
__device__ __forceinline__ float2 up2(unsigned long long v) {
    float2 r;
    asm("mov.b64 {%0, %1}, %2;" : "=f"(r.x), "=f"(r.y) : "l"(v));
    return r;
}
// tanh(v) = 1 - 2/(exp(2v)+1); saturates correctly at +-inf.
__device__ __forceinline__ float ftanh(float v) {
    float e = __expf(2.0f * v);
    return 1.0f - __fdividef(2.0f, e + 1.0f);
}

extern __shared__ float smem[];

__global__ void __launch_bounds__(NT, 1) maf_kernel(
    const float* __restrict__ x,   const float* __restrict__ ipar,
    const float* __restrict__ W1,  const float* __restrict__ b1,
    const float* __restrict__ W2,  const float* __restrict__ b2,
    const float* __restrict__ W3,  const float* __restrict__ b3,
    float* __restrict__ out, int out_size)
{
    float* xs  = smem;                     // [TB][XS_STR]
    float* w1s = xs  + TB * XS_STR;        // [KD][W1_STR] : dd*W1_STR + j*8 + h
    float* w2s = w1s + KD * W1_STR;        // [TL][W2_STR]
    float* w3s = w2s + TL * W2_STR;        // [TL][W3_STR]
    float* b1s = w3s + TL * W3_STR;        // [TL][8]
    float* b2s = b1s + TL * 8;             // [TL][8]
    float* b3s = b2s + TL * 8;             // [TL][2]

    const int tid    = threadIdx.x;
    const int warp   = tid >> 5;
    const int lane   = tid & 31;
    const int jw     = lane >> 3;          // 0..3 : j within warp
    const int rg     = lane & 7;           // 0..7 : row group within warp
    const int j      = (warp & 3) * 4 + jw;        // 0..15 layer lane
    const int rowset = warp >> 2;                  // 0/1 : which 64-row half
    const int rowbase = rowset * 64 + rg;          // rows rowbase + 8*i
    const int row0   = blockIdx.x * TB;

    // ---- load x tile (coalesced float4) ----
    {
        const float4* xg = (const float4*)(x + (size_t)row0 * DD);
        #pragma unroll
        for (int i = 0; i < (TB * DD / 4) / NT; ++i) {   // 32 iters
            int v  = tid + i * NT;
            int r  = v >> 6;
            int dv = v & 63;
            float4 val = xg[r * (DD / 4) + dv];
            *(float4*)(xs + r * XS_STR + dv * 4) = val;
        }
    }

    unsigned long long acc[8][4];          // 8 rows x 8 h (packed pairs)
    float asum[8];
    #pragma unroll
    for (int i = 0; i < 8; ++i) asum[i] = 0.f;

    for (int c = 0; c < 16; ++c) {
        const int l0 = c * TL;
        const int l  = l0 + j;
        __syncthreads();                   // previous chunk epilogue done

        // ---- per-layer small weights for this chunk ----
        {   // w2s: 16 layers x 64 floats = 256 float4, one per thread
            int jj = tid >> 4, q = tid & 15;
            float4 v4 = make_float4(0.f, 0.f, 0.f, 0.f);
            if (l0 + jj < LL) v4 = ((const float4*)W2)[(l0 + jj) * 16 + q];
            *(float4*)(w2s + jj * W2_STR + q * 4) = v4;
        }
        {   // w3s: 16 x 16 floats
            int jj = tid >> 4, hk = tid & 15;
            w3s[jj * W3_STR + hk] = (l0 + jj < LL) ? W3[(l0 + jj) * 16 + hk] : 0.f;
        }
        if (tid < TL * 8) {
            int jj = tid >> 3, h = tid & 7;
            b1s[tid] = (l0 + jj < LL) ? b1[(l0 + jj) * 8 + h] : 0.f;
            b2s[tid] = (l0 + jj < LL) ? b2[(l0 + jj) * 8 + h] : 0.f;
        }
        if (tid < TL * 2) {
            int jj = tid >> 1, k = tid & 1;
            b3s[tid] = (l0 + jj < LL) ? b3[(l0 + jj) * 2 + k] : 0.f;
        }

        #pragma unroll
        for (int i = 0; i < 8; ++i) {
            acc[i][0] = 0ull; acc[i][1] = 0ull; acc[i][2] = 0ull; acc[i][3] = 0ull;
        }

        // causal: chunk c needs d <= l0+15 -> sub-chunks of 32
        const int nsub = (l0 + TL + KD - 1) >> 5;
        for (int s = 0; s < nsub; ++s) {
            const int d0 = s << 5;
            __syncthreads();
            // ---- fill W1 sub-chunk (masked): 32dd x 16j x 8h = 1024 float4 ----
            #pragma unroll
            for (int i = 0; i < 4; ++i) {
                int v   = tid + i * NT;
                int jj  = v >> 6;
                int rem = v & 63;
                int dd  = rem >> 1;
                int h4  = (rem & 1) << 2;
                int lL  = l0 + jj;
                int gd  = d0 + dd;
                float4 val = make_float4(0.f, 0.f, 0.f, 0.f);
                if (lL < LL && gd <= lL)
                    val = *(const float4*)(W1 + ((size_t)lL * DD + gd) * HH + h4);
                *(float4*)(w1s + dd * W1_STR + jj * 8 + h4) = val;
            }
            __syncthreads();

            const float* wp = w1s + j * 8;
            #pragma unroll 2
            for (int dd4 = 0; dd4 < KD; dd4 += 4) {
                float4 xv[8];
                #pragma unroll
                for (int i = 0; i < 8; ++i)
                    xv[i] = *(const float4*)(xs + (rowbase + 8 * i) * XS_STR + d0 + dd4);
                #pragma unroll
                for (int u = 0; u < 4; ++u) {
                    ulonglong2 wA = *(const ulonglong2*)(wp + (dd4 + u) * W1_STR);
                    ulonglong2 wB = *(const ulonglong2*)(wp + (dd4 + u) * W1_STR + 4);
                    #pragma unroll
                    for (int i = 0; i < 8; ++i) {
                        const float* xp = (const float*)&xv[i];
                        float xu = xp[u];
                        unsigned long long p = pk2(xu, xu);
                        fma2(acc[i][0], p, wA.x);
                        fma2(acc[i][1], p, wA.y);
                        fma2(acc[i][2], p, wB.x);
                        fma2(acc[i][3], p, wB.y);
                    }
                }
            }
        }

        // ---- epilogue: tiny MLP + z write for layer l, 8 rows ----
        if (l < LL) {
            #pragma unroll
            for (int i = 0; i < 8; ++i) {
                float h1v[8];
                #pragma unroll
                for (int hp = 0; hp < 4; ++hp) {
                    float2 a = up2(acc[i][hp]);
                    h1v[2 * hp]     = ftanh(a.x + b1s[j * 8 + 2 * hp]);
                    h1v[2 * hp + 1] = ftanh(a.y + b1s[j * 8 + 2 * hp + 1]);
                }
                unsigned long long a2[4];
                a2[0] = pk2(b2s[j * 8 + 0], b2s[j * 8 + 1]);
                a2[1] = pk2(b2s[j * 8 + 2], b2s[j * 8 + 3]);
                a2[2] = pk2(b2s[j * 8 + 4], b2s[j * 8 + 5]);
                a2[3] = pk2(b2s[j * 8 + 6], b2s[j * 8 + 7]);
                #pragma unroll
                for (int h = 0; h < 8; ++h) {
                    ulonglong2 rA = *(const ulonglong2*)(w2s + j * W2_STR + h * 8);
                    ulonglong2 rB = *(const ulonglong2*)(w2s + j * W2_STR + h * 8 + 4);
                    unsigned long long hp = pk2(h1v[h], h1v[h]);
                    fma2(a2[0], hp, rA.x); fma2(a2[1], hp, rA.y);
                    fma2(a2[2], hp, rB.x); fma2(a2[3], hp, rB.y);
                }
                float mu = b3s[j * 2 + 0], al = b3s[j * 2 + 1];
                #pragma unroll
                for (int hp = 0; hp < 4; ++hp) {
                    float2 p = up2(a2[hp]);
                    float h2a = ftanh(p.x), h2b = ftanh(p.y);
                    mu += h2a * w3s[j * W3_STR + (2 * hp) * 2]
                        + h2b * w3s[j * W3_STR + (2 * hp + 1) * 2];
                    al += h2a * w3s[j * W3_STR + (2 * hp) * 2 + 1]
                        + h2b * w3s[j * W3_STR + (2 * hp + 1) * 2 + 1];
                }
                int row = rowbase + 8 * i;
                float xn = xs[row * XS_STR + (l + 1)];
                float zv = (xn - mu) * __expf(-al);
                out[(size_t)(row0 + row) * DD + (254 - l)] = zv;  // reversed col
                asum[i] += al;
            }
        }
    }

    // ---- reduce alpha partials across 16 layer lanes; finalize ----
    __syncthreads();
    #pragma unroll
    for (int i = 0; i < 8; ++i)
        w1s[(rowbase + 8 * i) * 17 + j] = asum[i];  // scratch [128][17]
    __syncthreads();
    if (tid < TB) {
        int row = tid;
        float ssum = 0.f;
        #pragma unroll
        for (int jj = 0; jj < 16; ++jj) ssum += w1s[row * 17 + jj];
        float ip0 = ipar[0], ip1 = ipar[1];
        out[(size_t)(row0 + row) * DD + 255] = (xs[row * XS_STR] - ip0) * __expf(-ip1);
        if (out_size > BB * DD)
            out[(size_t)BB * DD + row0 + row] = -(ip1 + ssum);
    }
}

extern "C" void kernel_launch(void* const* d_in, const int* in_sizes, int n_in,
                              void* d_out, int out_size)
{
    const float* x    = (const float*)d_in[0];
    const float* ipar = (const float*)d_in[1];
    const float* W1   = (const float*)d_in[2];
    const float* b1   = (const float*)d_in[3];
    const float* W2   = (const float*)d_in[4];
    const float* b2   = (const float*)d_in[5];
    const float* W3   = (const float*)d_in[6];
    const float* b3   = (const float*)d_in[7];
    float* out = (float*)d_out;

    cudaFuncSetAttribute(maf_kernel, cudaFuncAttributeMaxDynamicSharedMemorySize, SMEM_BYTES);
    maf_kernel<<<BB / TB, NT, SMEM_BYTES>>>(x, ipar, W1, b1, W2, b2, W3, b3, out, out_size);
}

// round 3
// speedup vs baseline: 1.5481x; 1.0332x over previous
#include <cuda_runtime.h>
#include <cstddef>

// Problem constants
#define BB 16384
#define DD 256
#define LL 255
#define HH 8

// Tiling
#define TB 64      // batch rows per CTA
#define TL 16      // layers per chunk
#define KD 32      // d sub-chunk granularity
#define NT 256     // threads per CTA

// Padded smem strides (floats)
#define XS_STR 260
#define W1_STR 132
#define W2_STR 68
#define W3_STR 18

#define SMEM_FLOATS (TB*XS_STR + KD*W1_STR + TL*W2_STR + TL*W3_STR + TL*8 + TL*8 + TL*2)
#define SMEM_BYTES  (SMEM_FLOATS * 4)

__device__ __forceinline__ unsigned long long pk2(float a, float b) {
    unsigned long long r;
    asm("mov.b64 %0, {%1, %2};" : "=l"(r) : "f"(a), "f"(b));
    return r;
}
__device__ __forceinline__ void fma2(unsigned long long& d, unsigned long long a, unsigned long long b) {
    asm("fma.rn.f32x2 %0, %1, %2, %0;" : "+l"(d) : "l"(a), "l"(b));
}
__device__ __forceinline__ float2 up2(unsigned long long v) {
    float2 r;
    asm("mov.b64 {%0, %1}, %2;" : "=f"(r.x), "=f"(r.y) : "l"(v));
    return r;
}
// tanh(v) = 1 - 2/(exp(2v)+1); saturates correctly at +-inf.
__device__ __forceinline__ float ftanh(float v) {
    float e = __expf(2.0f * v);
    return 1.0f - __fdividef(2.0f, e + 1.0f);
}

extern __shared__ float smem[];

__global__ void __launch_bounds__(NT, 2) maf_kernel(
    const float* __restrict__ x,   const float* __restrict__ ipar,
    const float* __restrict__ W1,  const float* __restrict__ b1,
    const float* __restrict__ W2,  const float* __restrict__ b2,
    const float* __restrict__ W3,  const float* __restrict__ b3,
    float* __restrict__ out, int out_size)
{
    float* xs  = smem;                     // [TB][XS_STR]
    float* w1s = xs  + TB * XS_STR;        // [KD][W1_STR] : dd*W1_STR + j*8 + h
    float* w2s = w1s + KD * W1_STR;        // [TL][W2_STR]
    float* w3s = w2s + TL * W2_STR;        // [TL][W3_STR]
    float* b1s = w3s + TL * W3_STR;        // [TL][8]
    float* b2s = b1s + TL * 8;             // [TL][8]
    float* b3s = b2s + TL * 8;             // [TL][2]

    const int tid    = threadIdx.x;
    const int warp   = tid >> 5;
    const int lane   = tid & 31;
    const int jw     = lane >> 3;                 // 0..3 : j within warp
    const int rg     = lane & 7;                  // 0..7 : row group within warp
    const int j      = (warp & 3) * 4 + jw;       // 0..15 layer lane
    const int rowhalf = warp >> 2;                // 0/1 : which 32-row half
    const int rowbase = rowhalf * 32 + rg;        // rows rowbase + 8*i (i<4)
    const int row0   = blockIdx.x * TB;

    // ---- load x tile (coalesced float4) ----
    {
        const float4* xg = (const float4*)(x + (size_t)row0 * DD);
        #pragma unroll
        for (int i = 0; i < (TB * DD / 4) / NT; ++i) {   // 16 iters
            int v  = tid + i * NT;
            int r  = v >> 6;
            int dv = v & 63;
            float4 val = xg[r * (DD / 4) + dv];
            *(float4*)(xs + r * XS_STR + dv * 4) = val;
        }
    }

    unsigned long long acc[4][4];          // 4 rows x 8 h (packed pairs)
    float asum[4] = {0.f, 0.f, 0.f, 0.f};

    for (int c = 0; c < 16; ++c) {
        const int l0 = c * TL;
        const int l  = l0 + j;
        __syncthreads();                   // previous chunk epilogue done

        // ---- per-layer small weights for this chunk ----
        {   // w2s: 16 layers x 64 floats = 256 float4, one per thread
            int jj = tid >> 4, q = tid & 15;
            float4 v4 = make_float4(0.f, 0.f, 0.f, 0.f);
            if (l0 + jj < LL) v4 = ((const float4*)W2)[(l0 + jj) * 16 + q];
            *(float4*)(w2s + jj * W2_STR + q * 4) = v4;
        }
        {   // w3s: 16 x 16 floats
            int jj = tid >> 4, hk = tid & 15;
            w3s[jj * W3_STR + hk] = (l0 + jj < LL) ? W3[(l0 + jj) * 16 + hk] : 0.f;
        }
        if (tid < TL * 8) {
            int jj = tid >> 3, h = tid & 7;
            b1s[tid] = (l0 + jj < LL) ? b1[(l0 + jj) * 8 + h] : 0.f;
            b2s[tid] = (l0 + jj < LL) ? b2[(l0 + jj) * 8 + h] : 0.f;
        }
        if (tid < TL * 2) {
            int jj = tid >> 1, k = tid & 1;
            b3s[tid] = (l0 + jj < LL) ? b3[(l0 + jj) * 2 + k] : 0.f;
        }

        #pragma unroll
        for (int i = 0; i < 4; ++i) {
            acc[i][0] = 0ull; acc[i][1] = 0ull; acc[i][2] = 0ull; acc[i][3] = 0ull;
        }

        // causal: chunk c needs d <= l0+15 -> sub-chunks of 32
        const int nsub = (l0 + TL + KD - 1) >> 5;
        for (int s = 0; s < nsub; ++s) {
            const int d0 = s << 5;
            __syncthreads();
            // ---- fill W1 sub-chunk (masked): 32dd x 16j x 8h = 1024 float4 ----
            #pragma unroll
            for (int i = 0; i < 4; ++i) {
                int v   = tid + i * NT;
                int jj  = v >> 6;
                int rem = v & 63;
                int dd  = rem >> 1;
                int h4  = (rem & 1) << 2;
                int lL  = l0 + jj;
                int gd  = d0 + dd;
                float4 val = make_float4(0.f, 0.f, 0.f, 0.f);
                if (lL < LL && gd <= lL)
                    val = *(const float4*)(W1 + ((size_t)lL * DD + gd) * HH + h4);
                *(float4*)(w1s + dd * W1_STR + jj * 8 + h4) = val;
            }
            __syncthreads();

            const float* wp = w1s + j * 8;
            #pragma unroll 2
            for (int dd4 = 0; dd4 < KD; dd4 += 4) {
                float4 xv[4];
                #pragma unroll
                for (int i = 0; i < 4; ++i)
                    xv[i] = *(const float4*)(xs + (rowbase + 8 * i) * XS_STR + d0 + dd4);
                #pragma unroll
                for (int u = 0; u < 4; ++u) {
                    ulonglong2 wA = *(const ulonglong2*)(wp + (dd4 + u) * W1_STR);
                    ulonglong2 wB = *(const ulonglong2*)(wp + (dd4 + u) * W1_STR + 4);
                    #pragma unroll
                    for (int i = 0; i < 4; ++i) {
                        const float* xp = (const float*)&xv[i];
                        float xu = xp[u];
                        unsigned long long p = pk2(xu, xu);
                        fma2(acc[i][0], p, wA.x);
                        fma2(acc[i][1], p, wA.y);
                        fma2(acc[i][2], p, wB.x);
                        fma2(acc[i][3], p, wB.y);
                    }
                }
            }
        }

        // ---- epilogue: tiny MLP + z write for layer l, 4 rows ----
        if (l < LL) {
            #pragma unroll
            for (int i = 0; i < 4; ++i) {
                float h1v[8];
                #pragma unroll
                for (int hp = 0; hp < 4; ++hp) {
                    float2 a = up2(acc[i][hp]);
                    h1v[2 * hp]     = ftanh(a.x + b1s[j * 8 + 2 * hp]);
                    h1v[2 * hp + 1] = ftanh(a.y + b1s[j * 8 + 2 * hp + 1]);
                }
                unsigned long long a2[4];
                a2[0] = pk2(b2s[j * 8 + 0], b2s[j * 8 + 1]);
                a2[1] = pk2(b2s[j * 8 + 2], b2s[j * 8 + 3]);
                a2[2] = pk2(b2s[j * 8 + 4], b2s[j * 8 + 5]);
                a2[3] = pk2(b2s[j * 8 + 6], b2s[j * 8 + 7]);
                #pragma unroll
                for (int h = 0; h < 8; ++h) {
                    ulonglong2 rA = *(const ulonglong2*)(w2s + j * W2_STR + h * 8);
                    ulonglong2 rB = *(const ulonglong2*)(w2s + j * W2_STR + h * 8 + 4);
                    unsigned long long hp = pk2(h1v[h], h1v[h]);
                    fma2(a2[0], hp, rA.x); fma2(a2[1], hp, rA.y);
                    fma2(a2[2], hp, rB.x); fma2(a2[3], hp, rB.y);
                }
                float mu = b3s[j * 2 + 0], al = b3s[j * 2 + 1];
                #pragma unroll
                for (int hp = 0; hp < 4; ++hp) {
                    float2 p = up2(a2[hp]);
                    float h2a = ftanh(p.x), h2b = ftanh(p.y);
                    mu += h2a * w3s[j * W3_STR + (2 * hp) * 2]
                        + h2b * w3s[j * W3_STR + (2 * hp + 1) * 2];
                    al += h2a * w3s[j * W3_STR + (2 * hp) * 2 + 1]
                        + h2b * w3s[j * W3_STR + (2 * hp + 1) * 2 + 1];
                }
                int row = rowbase + 8 * i;
                float xn = xs[row * XS_STR + (l + 1)];
                float zv = (xn - mu) * __expf(-al);
                out[(size_t)(row0 + row) * DD + (254 - l)] = zv;  // reversed col
                asum[i] += al;
            }
        }
    }

    // ---- reduce alpha partials across 16 layer lanes; finalize ----
    __syncthreads();
    #pragma unroll
    for (int i = 0; i < 4; ++i)
        w1s[(rowbase + 8 * i) * 17 + j] = asum[i];  // scratch [64][17]
    __syncthreads();
    if (tid < TB) {
        int row = tid;
        float ssum = 0.f;
        #pragma unroll
        for (int jj = 0; jj < 16; ++jj) ssum += w1s[row * 17 + jj];
        float ip0 = ipar[0], ip1 = ipar[1];
        out[(size_t)(row0 + row) * DD + 255] = (xs[row * XS_STR] - ip0) * __expf(-ip1);
        if (out_size > BB * DD)
            out[(size_t)BB * DD + row0 + row] = -(ip1 + ssum);
    }
}

extern "C" void kernel_launch(void* const* d_in, const int* in_sizes, int n_in,
                              void* d_out, int out_size)
{
    const float* x    = (const float*)d_in[0];
    const float* ipar = (const float*)d_in[1];
    const float* W1   = (const float*)d_in[2];
    const float* b1   = (const float*)d_in[3];
    const float* W2   = (const float*)d_in[4];
    const float* b2   = (const float*)d_in[5];
    const float* W3   = (const float*)d_in[6];
    const float* b3   = (const float*)d_in[7];
    float* out = (float*)d_out;

    cudaFuncSetAttribute(maf_kernel, cudaFuncAttributeMaxDynamicSharedMemorySize, SMEM_BYTES);
    maf_kernel<<<BB / TB, NT, SMEM_BYTES>>>(x, ipar, W1, b1, W2, b2, W3, b3, out, out_size);
}